// round 8
// baseline (speedup 1.0000x reference)
#include <cuda_runtime.h>
#include <cuda_fp16.h>
#include <cstdint>

// Problem constants: P=8 segments, L=512 codes, D=64, N=1M tokens.
#define PP 8
#define LLEN 512
#define DD 64
#define CC (PP * LLEN)   // 4096 rows in transposed table

// Transposed + fp16-converted table: g_Wh[c][d] = (half)W[d][c]. 512 KB.
__device__ __half g_Wh[CC * DD];

// ---------------------------------------------------------------------------
// Transpose+convert W [D=64, C=4096] fp32 -> g_Wh [C=4096, D=64] fp16.
// ---------------------------------------------------------------------------
__global__ void convert_w_kernel(const float* __restrict__ W) {
    int c = blockIdx.x * blockDim.x + threadIdx.x;   // 0 .. 4095
    if (c >= CC) return;

    __half hbuf[DD];
#pragma unroll
    for (int d = 0; d < DD; d++) {
        hbuf[d] = __float2half(W[d * CC + c]);
    }
    uint4* dst = reinterpret_cast<uint4*>(g_Wh + (size_t)c * DD);
    const uint4* src = reinterpret_cast<const uint4*>(hbuf);
#pragma unroll
    for (int k = 0; k < 8; k++) dst[k] = src[k];
}

// fp16 two-level tree + fp32 finish on 8 gathered 8B slots.
__device__ __forceinline__ float4
reduce8(const uint2& v0, const uint2& v1, const uint2& v2, const uint2& v3,
        const uint2& v4, const uint2& v5, const uint2& v6, const uint2& v7) {
    const __half2* h0 = reinterpret_cast<const __half2*>(&v0);
    const __half2* h1 = reinterpret_cast<const __half2*>(&v1);
    const __half2* h2 = reinterpret_cast<const __half2*>(&v2);
    const __half2* h3 = reinterpret_cast<const __half2*>(&v3);
    const __half2* h4 = reinterpret_cast<const __half2*>(&v4);
    const __half2* h5 = reinterpret_cast<const __half2*>(&v5);
    const __half2* h6 = reinterpret_cast<const __half2*>(&v6);
    const __half2* h7 = reinterpret_cast<const __half2*>(&v7);
    float res[4];
#pragma unroll
    for (int k = 0; k < 2; k++) {
        __half2 w01 = __hadd2(h0[k], h1[k]);
        __half2 w23 = __hadd2(h2[k], h3[k]);
        __half2 w45 = __hadd2(h4[k], h5[k]);
        __half2 w67 = __hadd2(h6[k], h7[k]);
        __half2 u0 = __hadd2(w01, w23);
        __half2 u1 = __hadd2(w45, w67);
        float2 f0 = __half22float2(u0);
        float2 f1 = __half22float2(u1);
        res[2 * k + 0] = f0.x + f1.x;
        res[2 * k + 1] = f0.y + f1.y;
    }
    return make_float4(res[0], res[1], res[2], res[3]);
}

// ---------------------------------------------------------------------------
// Persistent gather-and-sum with index prefetch.
// Lane layout (as R5 best): warp = 2 tokens/iteration, t = lane>>4 selects
// the token, s = lane&15 the 8B slot of the 128B table row; each gather is
// one LDG.64 covering both tokens' row p (2 lines/instr).
// Steady-state chain per iteration no longer contains the idx load: the next
// pair's indices are fetched (clamped address, no branch) while the current
// gathers are still in flight.
// ---------------------------------------------------------------------------
__global__ void __launch_bounds__(256)
eif_gather_h_kernel(const int* __restrict__ x, float* __restrict__ out,
                    int n_tok, int n_pairs) {
    int gwarp = (blockIdx.x * blockDim.x + threadIdx.x) >> 5;
    int nwarp = (gridDim.x * blockDim.x) >> 5;
    int lane  = threadIdx.x & 31;
    int t     = lane >> 4;
    int s     = lane & 15;

    const uint2* __restrict__ Wb = reinterpret_cast<const uint2*>(g_Wh) + s;
    const int4*  __restrict__ xv = reinterpret_cast<const int4*>(x);

    int pair = gwarp;
    if (pair >= n_pairs) return;

    // Load first pair's indices (this token = pair*2 + t).
    int tok = pair * 2 + t;
    int tl  = tok < n_tok ? tok : n_tok - 1;     // clamp (odd-N safety)
    int4 i0 = xv[tl * 2 + 0];
    int4 i1 = xv[tl * 2 + 1];

    for (;;) {
        // 1) Issue this iteration's 8 gathers (LDG.64, MLP=8).
        uint2 v0 = Wb[(size_t)(0 * LLEN + i0.x) * 16];
        uint2 v1 = Wb[(size_t)(1 * LLEN + i0.y) * 16];
        uint2 v2 = Wb[(size_t)(2 * LLEN + i0.z) * 16];
        uint2 v3 = Wb[(size_t)(3 * LLEN + i0.w) * 16];
        uint2 v4 = Wb[(size_t)(4 * LLEN + i1.x) * 16];
        uint2 v5 = Wb[(size_t)(5 * LLEN + i1.y) * 16];
        uint2 v6 = Wb[(size_t)(6 * LLEN + i1.z) * 16];
        uint2 v7 = Wb[(size_t)(7 * LLEN + i1.w) * 16];

        // 2) Prefetch next pair's indices NOW (clamped address -> always
        //    issuable, independent of the gathers above).
        int next   = pair + nwarp;
        int ntok   = next * 2 + t;
        int ncl    = ntok < n_tok ? ntok : n_tok - 1;
        int4 n0    = xv[ncl * 2 + 0];
        int4 n1    = xv[ncl * 2 + 1];

        // 3) Reduce + store current pair.
        float4 r = reduce8(v0, v1, v2, v3, v4, v5, v6, v7);
        if (tok < n_tok) {
            __stcs(reinterpret_cast<float4*>(out + (size_t)tok * DD) + s, r);
        }

        // 4) Advance.
        if (next >= n_pairs) break;
        pair = next;
        tok  = ntok;
        i0   = n0;
        i1   = n1;
    }
}

// ---------------------------------------------------------------------------
// kernel_launch: d_in[0] = x (int32, N*8), d_in[1] = W (float32, 64*4096).
// ---------------------------------------------------------------------------
extern "C" void kernel_launch(void* const* d_in, const int* in_sizes, int n_in,
                              void* d_out, int out_size) {
    const int*   x = (const int*)d_in[0];
    const float* W = (const float*)d_in[1];
    float*       out = (float*)d_out;

    int n_tok   = in_sizes[0] / PP;          // N
    int n_pairs = (n_tok + 1) / 2;

    // 1) Convert + transpose table to fp16.
    convert_w_kernel<<<(CC + 255) / 256, 256>>>(W);

    // 2) Persistent gather-and-sum: 148 SMs x 8 CTAs, 256 threads each.
    {
        int grid = 148 * 8;                  // 1184 CTAs, 9472 warps
        eif_gather_h_kernel<<<grid, 256>>>(x, out, n_tok, n_pairs);
    }
}